// round 13
// baseline (speedup 1.0000x reference)
#include <cuda_runtime.h>
#include <cuda_bf16.h>
#include <cstdint>

#define NTHREADS 256
#define TB       32
#define OMEGA_F  30.0f

// ---------------- helpers ----------------
static __device__ __forceinline__ uint32_t smem_u32(const void* p) {
    uint32_t a;
    asm("{ .reg .u64 t; cvta.to.shared.u64 t, %1; cvt.u32.u64 %0, t; }" : "=r"(a) : "l"(p));
    return a;
}
static __device__ __forceinline__ void ldsm_x4(uint32_t* r, uint32_t a) {
    asm volatile("ldmatrix.sync.aligned.m8n8.x4.shared.b16 {%0,%1,%2,%3}, [%4];"
        : "=r"(r[0]), "=r"(r[1]), "=r"(r[2]), "=r"(r[3]) : "r"(a));
}
static __device__ __forceinline__ void ldsm_x2(uint32_t* r, uint32_t a) {
    asm volatile("ldmatrix.sync.aligned.m8n8.x2.shared.b16 {%0,%1}, [%2];"
        : "=r"(r[0]), "=r"(r[1]) : "r"(a));
}
static __device__ __forceinline__ void mma16816(float* d, const uint32_t* a, const uint32_t* b) {
    asm volatile("mma.sync.aligned.m16n8k16.row.col.f32.bf16.bf16.f32 "
        "{%0,%1,%2,%3}, {%4,%5,%6,%7}, {%8,%9}, {%0,%1,%2,%3};"
        : "+f"(d[0]), "+f"(d[1]), "+f"(d[2]), "+f"(d[3])
        : "r"(a[0]), "r"(a[1]), "r"(a[2]), "r"(a[3]), "r"(b[0]), "r"(b[1]));
}
static __device__ __forceinline__ void split_pair(float a0, float a1, uint32_t& hi, uint32_t& lo) {
    __nv_bfloat16 h0 = __float2bfloat16(a0), h1 = __float2bfloat16(a1);
    __nv_bfloat16 q0 = __float2bfloat16(a0 - __bfloat162float(h0));
    __nv_bfloat16 q1 = __float2bfloat16(a1 - __bfloat162float(h1));
    hi = ((uint32_t)__bfloat16_as_ushort(h1) << 16) | __bfloat16_as_ushort(h0);
    lo = ((uint32_t)__bfloat16_as_ushort(q1) << 16) | __bfloat16_as_ushort(q0);
}
static __device__ __forceinline__ float join_w(uint32_t h, uint32_t l, int hi16) {
    unsigned short hs = hi16 ? (unsigned short)(h >> 16) : (unsigned short)(h & 0xFFFF);
    unsigned short ls = hi16 ? (unsigned short)(l >> 16) : (unsigned short)(l & 0xFFFF);
    return __bfloat162float(__ushort_as_bfloat16(hs)) + __bfloat162float(__ushort_as_bfloat16(ls));
}
static __device__ __forceinline__ uint32_t abyteA(int m, int k, int SK) {
    return (uint32_t)m * (uint32_t)(SK * 2)
         + (uint32_t)((((k >> 3) ^ (m & 7)) << 4) + (k & 7) * 2);
}

// ---------------- weight blob (pre-split hi/lo, pre-swizzled) ----------------
#define BO_ENC1 0
#define BO_ENC2 32768
#define BO_RES1 163840
#define BO_RES2 294912
#define BO_RES3 360448
#define BO_POL2 491520
#define BO_EXP1 557056
#define BO_EXP2 2392064
#define BLOB_BYTES 4227072
__device__ __align__(16) uint8_t g_blob[BLOB_BYTES];

struct RefSeg { const float* src; int off; int N; int K; };
__global__ void reformat_all(RefSeg s0, RefSeg s1, RefSeg s2, RefSeg s3,
                             RefSeg s4, RefSeg s5, RefSeg s6, RefSeg s7)
{
    int idx = blockIdx.x * blockDim.x + threadIdx.x;
    RefSeg s; int local;
    if      (idx <   8192) { s = s0; local = idx; }
    else if (idx <  40960) { s = s1; local = idx - 8192; }
    else if (idx <  73728) { s = s2; local = idx - 40960; }
    else if (idx <  90112) { s = s3; local = idx - 73728; }
    else if (idx < 122880) { s = s4; local = idx - 90112; }
    else if (idx < 139264) { s = s5; local = idx - 122880; }
    else if (idx < 598016) { s = s6; local = idx - 139264; }
    else if (idx < 1056768){ s = s7; local = idx - 598016; }
    else return;
    const int N = s.N, K = s.K;
    int k  = local % K;
    int n  = (local / K) % N;
    int nb = local / (K * N);
    float w = s.src[local];
    __nv_bfloat16 h = __float2bfloat16(w);
    __nv_bfloat16 l = __float2bfloat16(w - __bfloat162float(h));
    int per_nb = (K / 64) * 2 * (N * 128);
    int kc = k >> 6, kk = k & 63;
    int base = s.off + nb * per_nb + kc * 2 * (N * 128);
    uint32_t byte = (uint32_t)n * 128u + (uint32_t)((((kk >> 3) ^ (n & 7)) << 4) + (kk & 7) * 2);
    *(__nv_bfloat16*)(g_blob + base + byte)           = h;
    *(__nv_bfloat16*)(g_blob + base + N * 128 + byte) = l;
}

// ---------------- SMEM layout (bytes) per CTA ----------------
#define SMB_W0    0         // single 32KB weight buffer
#define SMB_ABH   32768     // A_big hi [32][<=256] bf16 (16KB)
#define SMB_ABL   49152
#define SMB_AEH   65536     // A_exp hi (16KB)
#define SMB_AEL   81920
#define SMB_XS    98304     // [4][32] f32
#define SMB_PROBS 98816     // [7][32] f32
#define SMB_YACC  99712     // [32] f32
#define SMB_SCR   99840     // [4][32] f32
#define SMB_TOTAL 100352

// ---------------- fused MMA layer ----------------
// 8 warps: warp_m = warp&1 (16 rows each), warp_n = warp>>1 (N/4 cols each)
// Single W buffer: [store][syncA][prefetch next + MMA][syncB] per fill.
// MODE 0: sin->dest  1: relu->dest  2: relu(D+b+dest)->dest  3: sin·extra -> scr
template <int K, int N, int MODE, int SKA, int SKD>
static __device__ void layer(char* smem, const uint8_t* blob,
                             uint32_t aHi, uint32_t aLo,
                             char* dHi, char* dLo,
                             const float* bias, const float* extra)
{
    constexpr int FILLS = (K / 64) * 2;
    constexpr int LD = N / 32;      // uint4 per thread per fill (N*128B / 256thr / 16B)
    constexpr int NT = N / 32;      // 8-wide n tiles per warp
    const int tid = threadIdx.x, lane = tid & 31, warp = tid >> 5;
    const int warp_m = warp & 1, warp_n = warp >> 1;
    const int nh = warp_n * (N / 4);

    float d[NT][4];
#pragma unroll
    for (int nt = 0; nt < NT; nt++)
#pragma unroll
        for (int i = 0; i < 4; i++) d[nt][i] = 0.0f;

    const int mlocal = (lane & 7) + ((lane >> 3) & 1) * 8;
    const int chA = lane >> 4;
    const int bi = lane & 7, bsel = (lane >> 3) & 1;
    const int mA = warp_m * 16 + mlocal;
    const uint32_t wb = smem_u32(smem + SMB_W0);
    uint4* ws = (uint4*)(smem + SMB_W0);
    const uint4* gsrc = (const uint4*)blob;

    uint4 pf[LD];
#pragma unroll
    for (int l = 0; l < LD; l++) pf[l] = __ldg(gsrc + tid + NTHREADS * l);

    for (int f = 0; f < FILLS; f++) {
#pragma unroll
        for (int l = 0; l < LD; l++) ws[tid + NTHREADS * l] = pf[l];
        __syncthreads();                       // stores visible
        if (f + 1 < FILLS) {
            const uint4* s2 = gsrc + (size_t)(f + 1) * (N * 8);
#pragma unroll
            for (int l = 0; l < LD; l++) pf[l] = __ldg(s2 + tid + NTHREADS * l);
        }
        const int kc = f >> 1, whalf = f & 1;
#pragma unroll
        for (int kk4 = 0; kk4 < 4; kk4++) {
            const int k0 = kc * 64 + kk4 * 16;
            uint32_t ah[4], al[4];
            const uint32_t offA = (uint32_t)mA * (uint32_t)(SKA * 2)
                + (uint32_t)(((((k0 >> 3) + chA) ^ (mA & 7)) << 4));
            ldsm_x4(ah, aHi + offA);
            if (!whalf) ldsm_x4(al, aLo + offA);
#pragma unroll
            for (int nt = 0; nt < NT; nt++) {
                const int n = nh + nt * 8 + bi;
                const uint32_t boff = (uint32_t)n * 128u
                    + (uint32_t)((((kk4 * 2 + bsel) ^ (n & 7)) << 4));
                uint32_t b[2];
                ldsm_x2(b, wb + boff);
                mma16816(d[nt], ah, b);
                if (!whalf) mma16816(d[nt], al, b);
            }
        }
        __syncthreads();                       // use done before next store
    }

    float pred[2] = {0.0f, 0.0f};
    const int m1 = warp_m * 16 + (lane >> 2);
    const int m2 = m1 + 8;
#pragma unroll
    for (int nt = 0; nt < NT; nt++) {
        const int nc = nh + nt * 8 + 2 * (lane & 3);
        const float b0 = __ldg(bias + nc), b1 = __ldg(bias + nc + 1);
        float v00 = d[nt][0] + b0, v01 = d[nt][1] + b1;
        float v10 = d[nt][2] + b0, v11 = d[nt][3] + b1;
        if (MODE == 3) {
            const float w0 = __ldg(extra + nc), w1 = __ldg(extra + nc + 1);
            pred[0] += w0 * __sinf(OMEGA_F * v00) + w1 * __sinf(OMEGA_F * v01);
            pred[1] += w0 * __sinf(OMEGA_F * v10) + w1 * __sinf(OMEGA_F * v11);
        } else {
            const uint32_t o1 = abyteA(m1, nc, SKD);
            const uint32_t o2 = abyteA(m2, nc, SKD);
            if (MODE == 2) {
                uint32_t hh = *(uint32_t*)(dHi + o1), ll = *(uint32_t*)(dLo + o1);
                v00 += join_w(hh, ll, 0); v01 += join_w(hh, ll, 1);
                hh = *(uint32_t*)(dHi + o2); ll = *(uint32_t*)(dLo + o2);
                v10 += join_w(hh, ll, 0); v11 += join_w(hh, ll, 1);
            }
            float s00, s01, s10, s11;
            if (MODE == 0) {
                s00 = __sinf(OMEGA_F * v00); s01 = __sinf(OMEGA_F * v01);
                s10 = __sinf(OMEGA_F * v10); s11 = __sinf(OMEGA_F * v11);
            } else {
                s00 = fmaxf(v00, 0.0f); s01 = fmaxf(v01, 0.0f);
                s10 = fmaxf(v10, 0.0f); s11 = fmaxf(v11, 0.0f);
            }
            uint32_t hi, lo;
            split_pair(s00, s01, hi, lo);
            *(uint32_t*)(dHi + o1) = hi; *(uint32_t*)(dLo + o1) = lo;
            split_pair(s10, s11, hi, lo);
            *(uint32_t*)(dHi + o2) = hi; *(uint32_t*)(dLo + o2) = lo;
        }
    }
    if (MODE == 3) {
        float* scr = (float*)(smem + SMB_SCR);
#pragma unroll
        for (int h = 0; h < 2; h++) {
            float p = pred[h];
            p += __shfl_xor_sync(0xFFFFFFFFu, p, 1);
            p += __shfl_xor_sync(0xFFFFFFFFu, p, 2);
            if ((lane & 3) == 0)
                scr[warp_n * 32 + warp_m * 16 + (lane >> 2) + h * 8] = p;
        }
    }
}

// ---------------- main kernel ----------------
__global__ void __launch_bounds__(NTHREADS, 2)
moe_inr_kernel(
    const float* __restrict__ x,
    const float* __restrict__ enc_s1_b, const float* __restrict__ enc_s2_b,
    const float* __restrict__ res_fc1_b, const float* __restrict__ res_fc2_b,
    const float* __restrict__ res_fc3_b,
    const float* __restrict__ pol_s1_w, const float* __restrict__ pol_s1_b,
    const float* __restrict__ pol_s2_b,
    const float* __restrict__ gate_w, const float* __restrict__ gate_b,
    const float* __restrict__ exp_s1_b, const float* __restrict__ exp_s2_b,
    const float* __restrict__ exp_fin_w, const float* __restrict__ exp_fin_b,
    float* __restrict__ out)
{
    extern __shared__ char smem[];
    const int tid = threadIdx.x;
    const long long rowbase = (long long)blockIdx.x * TB;
    float* xs    = (float*)(smem + SMB_XS);
    float* probs = (float*)(smem + SMB_PROBS);
    float* yacc  = (float*)(smem + SMB_YACC);
    float* scr   = (float*)(smem + SMB_SCR);
    char* abh = smem + SMB_ABH; char* abl = smem + SMB_ABL;
    char* aeh = smem + SMB_AEH; char* ael = smem + SMB_AEL;
    const uint32_t uABH = smem_u32(abh), uABL = smem_u32(abl);
    const uint32_t uAEH = smem_u32(aeh), uAEL = smem_u32(ael);

    if (tid < TB * 4) {
        int m = tid >> 2, dd = tid & 3;
        xs[dd * TB + m] = x[(rowbase + m) * 4 + dd];
    }
    __syncthreads();

    // positional encoding -> A_big (SK=64): col c = d*16+f, f<8 sin else cos
    for (int i = tid; i < TB * 32; i += NTHREADS) {     // 32 colpairs x TB rows
        int m = i & (TB - 1), jp = i / TB;
        int c0 = 2 * jp;
        float v[2];
#pragma unroll
        for (int t = 0; t < 2; t++) {
            int c = c0 + t, dd = c >> 4, f = c & 15;
            float ang = xs[dd * TB + m] * exp2f((float)(f & 7)) * 3.14159265358979323846f;
            v[t] = (f < 8) ? sinf(ang) : cosf(ang);
        }
        uint32_t hi, lo;
        split_pair(v[0], v[1], hi, lo);
        uint32_t off = abyteA(m, c0, 64);
        *(uint32_t*)(abh + off) = hi;
        *(uint32_t*)(abl + off) = lo;
    }
    __syncthreads();

    // encoder
    layer< 64, 128, 0,  64, 128>(smem, g_blob + BO_ENC1, uABH, uABL, aeh, ael, enc_s1_b, nullptr);
    __syncthreads();
    layer<128, 256, 0, 128, 256>(smem, g_blob + BO_ENC2, uAEH, uAEL, abh, abl, enc_s2_b, nullptr);
    __syncthreads();
    layer<256, 128, 1, 256, 128>(smem, g_blob + BO_RES1, uABH, uABL, aeh, ael, res_fc1_b, nullptr);
    __syncthreads();
    layer<128, 128, 1, 128, 128>(smem, g_blob + BO_RES2, uAEH, uAEL, aeh, ael, res_fc2_b, nullptr);
    __syncthreads();
    layer<128, 256, 2, 128, 256>(smem, g_blob + BO_RES3, uAEH, uAEL, abh, abl, res_fc3_b, nullptr);
    __syncthreads();

    // pol_s1 (K=4) scalar -> A_exp (SK=128)
    for (int i = tid; i < TB * 64; i += NTHREADS) {     // 64 colpairs x TB rows
        int m = i & (TB - 1), np = i / TB;
        int n0 = 2 * np;
        float x0 = xs[m], x1 = xs[TB + m], x2 = xs[2 * TB + m], x3 = xs[3 * TB + m];
        float4 w0 = __ldg((const float4*)pol_s1_w + n0);
        float4 w1 = __ldg((const float4*)pol_s1_w + n0 + 1);
        float z0 = __ldg(pol_s1_b + n0)     + x0 * w0.x + x1 * w0.y + x2 * w0.z + x3 * w0.w;
        float z1 = __ldg(pol_s1_b + n0 + 1) + x0 * w1.x + x1 * w1.y + x2 * w1.z + x3 * w1.w;
        uint32_t hi, lo;
        split_pair(__sinf(OMEGA_F * z0), __sinf(OMEGA_F * z1), hi, lo);
        uint32_t off = abyteA(m, n0, 128);
        *(uint32_t*)(aeh + off) = hi;
        *(uint32_t*)(ael + off) = lo;
    }
    __syncthreads();

    layer<128, 128, 0, 128, 128>(smem, g_blob + BO_POL2, uAEH, uAEL, aeh, ael, pol_s2_b, nullptr);
    __syncthreads();

    // gate + softmax (1 thread per row)
    if (tid < TB) {
        const int m = tid;
        float lg[7];
#pragma unroll
        for (int c = 0; c < 7; c++) lg[c] = __ldg(gate_b + c);
        for (int k2 = 0; k2 < 128; k2++) {
            uint32_t off = abyteA(m, 2 * k2, 256);
            uint32_t hh = *(uint32_t*)(abh + off), ll = *(uint32_t*)(abl + off);
            float e0 = join_w(hh, ll, 0), e1 = join_w(hh, ll, 1);
#pragma unroll
            for (int c = 0; c < 7; c++)
                lg[c] += e0 * __ldg(gate_w + c * 384 + 2 * k2)
                       + e1 * __ldg(gate_w + c * 384 + 2 * k2 + 1);
        }
        for (int k2 = 0; k2 < 64; k2++) {
            uint32_t off = abyteA(m, 2 * k2, 128);
            uint32_t hh = *(uint32_t*)(aeh + off), ll = *(uint32_t*)(ael + off);
            float p0 = join_w(hh, ll, 0), p1 = join_w(hh, ll, 1);
#pragma unroll
            for (int c = 0; c < 7; c++)
                lg[c] += p0 * __ldg(gate_w + c * 384 + 256 + 2 * k2)
                       + p1 * __ldg(gate_w + c * 384 + 256 + 2 * k2 + 1);
        }
        float mx = -1e30f;
#pragma unroll
        for (int c = 0; c < 7; c++) mx = fmaxf(mx, lg[c]);
        float s = 0.0f;
#pragma unroll
        for (int c = 0; c < 7; c++) { lg[c] = __expf(lg[c] - mx); s += lg[c]; }
        float inv = 1.0f / s;
#pragma unroll
        for (int c = 0; c < 7; c++) probs[c * TB + m] = lg[c] * inv;
        yacc[m] = 0.0f;
    }
    __syncthreads();

    // experts
    for (int e = 0; e < 7; e++) {
        layer<256, 256, 0, 256, 256>(smem, g_blob + BO_EXP1 + e * 262144,
                                     uABH, uABL, aeh, ael, exp_s1_b + e * 256, nullptr);
        __syncthreads();
        layer<256, 256, 3, 256, 256>(smem, g_blob + BO_EXP2 + e * 262144,
                                     uAEH, uAEL, nullptr, nullptr,
                                     exp_s2_b + e * 256, exp_fin_w + e * 256);
        __syncthreads();
        if (tid < TB) {
            float pred = scr[tid] + scr[TB + tid] + scr[2 * TB + tid] + scr[3 * TB + tid]
                       + __ldg(exp_fin_b + e);
            yacc[tid] += probs[e * TB + tid] * pred;
        }
        __syncthreads();
    }

    if (tid < TB) out[rowbase + tid] = yacc[tid];
}

// ---------------- host ----------------
extern "C" void kernel_launch(void* const* d_in, const int* in_sizes, int n_in,
                              void* d_out, int out_size)
{
    const float* x         = (const float*)d_in[0];
    const float* enc_s1_w  = (const float*)d_in[1];
    const float* enc_s1_b  = (const float*)d_in[2];
    const float* enc_s2_w  = (const float*)d_in[3];
    const float* enc_s2_b  = (const float*)d_in[4];
    const float* res_fc1_w = (const float*)d_in[5];
    const float* res_fc1_b = (const float*)d_in[6];
    const float* res_fc2_w = (const float*)d_in[7];
    const float* res_fc2_b = (const float*)d_in[8];
    const float* res_fc3_w = (const float*)d_in[9];
    const float* res_fc3_b = (const float*)d_in[10];
    const float* pol_s1_w  = (const float*)d_in[11];
    const float* pol_s1_b  = (const float*)d_in[12];
    const float* pol_s2_w  = (const float*)d_in[13];
    const float* pol_s2_b  = (const float*)d_in[14];
    const float* gate_w    = (const float*)d_in[15];
    const float* gate_b    = (const float*)d_in[16];
    const float* exp_s1_w  = (const float*)d_in[17];
    const float* exp_s1_b  = (const float*)d_in[18];
    const float* exp_s2_w  = (const float*)d_in[19];
    const float* exp_s2_b  = (const float*)d_in[20];
    const float* exp_fin_w = (const float*)d_in[21];
    const float* exp_fin_b = (const float*)d_in[22];

    RefSeg s0 = {enc_s1_w,  BO_ENC1, 128,  64};
    RefSeg s1 = {enc_s2_w,  BO_ENC2, 256, 128};
    RefSeg s2 = {res_fc1_w, BO_RES1, 128, 256};
    RefSeg s3 = {res_fc2_w, BO_RES2, 128, 128};
    RefSeg s4 = {res_fc3_w, BO_RES3, 256, 128};
    RefSeg s5 = {pol_s2_w,  BO_POL2, 128, 128};
    RefSeg s6 = {exp_s1_w,  BO_EXP1, 256, 256};
    RefSeg s7 = {exp_s2_w,  BO_EXP2, 256, 256};
    reformat_all<<<(1056768 + 255) / 256, 256>>>(s0, s1, s2, s3, s4, s5, s6, s7);

    int B = in_sizes[0] / 4;
    int grid = B / TB;
    cudaFuncSetAttribute(moe_inr_kernel, cudaFuncAttributeMaxDynamicSharedMemorySize, SMB_TOTAL);
    moe_inr_kernel<<<grid, NTHREADS, SMB_TOTAL>>>(
        x, enc_s1_b, enc_s2_b, res_fc1_b, res_fc2_b, res_fc3_b,
        pol_s1_w, pol_s1_b, pol_s2_b, gate_w, gate_b,
        exp_s1_b, exp_s2_b, exp_fin_w, exp_fin_b, (float*)d_out);
}

// round 14
// speedup vs baseline: 1.0993x; 1.0993x over previous
#include <cuda_runtime.h>
#include <cuda_bf16.h>
#include <cstdint>

#define NTHREADS 256
#define TB       64
#define OMEGA_F  30.0f

// ---------------- helpers ----------------
static __device__ __forceinline__ uint32_t smem_u32(const void* p) {
    uint32_t a;
    asm("{ .reg .u64 t; cvta.to.shared.u64 t, %1; cvt.u32.u64 %0, t; }" : "=r"(a) : "l"(p));
    return a;
}
static __device__ __forceinline__ void ldsm_x4(uint32_t* r, uint32_t a) {
    asm volatile("ldmatrix.sync.aligned.m8n8.x4.shared.b16 {%0,%1,%2,%3}, [%4];"
        : "=r"(r[0]), "=r"(r[1]), "=r"(r[2]), "=r"(r[3]) : "r"(a));
}
static __device__ __forceinline__ void ldsm_x2(uint32_t* r, uint32_t a) {
    asm volatile("ldmatrix.sync.aligned.m8n8.x2.shared.b16 {%0,%1}, [%2];"
        : "=r"(r[0]), "=r"(r[1]) : "r"(a));
}
static __device__ __forceinline__ void mma16816(float* d, const uint32_t* a, const uint32_t* b) {
    asm volatile("mma.sync.aligned.m16n8k16.row.col.f32.bf16.bf16.f32 "
        "{%0,%1,%2,%3}, {%4,%5,%6,%7}, {%8,%9}, {%0,%1,%2,%3};"
        : "+f"(d[0]), "+f"(d[1]), "+f"(d[2]), "+f"(d[3])
        : "r"(a[0]), "r"(a[1]), "r"(a[2]), "r"(a[3]), "r"(b[0]), "r"(b[1]));
}
static __device__ __forceinline__ void cpasync16(uint32_t dst, const void* src) {
    asm volatile("cp.async.cg.shared.global [%0], [%1], 16;" :: "r"(dst), "l"(src));
}
#define CP_COMMIT() asm volatile("cp.async.commit_group;" ::: "memory")
#define CP_WAIT0()  asm volatile("cp.async.wait_group 0;" ::: "memory")

static __device__ __forceinline__ void split_pair(float a0, float a1, uint32_t& hi, uint32_t& lo) {
    __nv_bfloat16 h0 = __float2bfloat16(a0), h1 = __float2bfloat16(a1);
    __nv_bfloat16 q0 = __float2bfloat16(a0 - __bfloat162float(h0));
    __nv_bfloat16 q1 = __float2bfloat16(a1 - __bfloat162float(h1));
    hi = ((uint32_t)__bfloat16_as_ushort(h1) << 16) | __bfloat16_as_ushort(h0);
    lo = ((uint32_t)__bfloat16_as_ushort(q1) << 16) | __bfloat16_as_ushort(q0);
}
static __device__ __forceinline__ float join_w(uint32_t h, uint32_t l, int hi16) {
    unsigned short hs = hi16 ? (unsigned short)(h >> 16) : (unsigned short)(h & 0xFFFF);
    unsigned short ls = hi16 ? (unsigned short)(l >> 16) : (unsigned short)(l & 0xFFFF);
    return __bfloat162float(__ushort_as_bfloat16(hs)) + __bfloat162float(__ushort_as_bfloat16(ls));
}
static __device__ __forceinline__ uint32_t abyteA(int m, int k, int SK) {
    return (uint32_t)m * (uint32_t)(SK * 2)
         + (uint32_t)((((k >> 3) ^ (m & 7)) << 4) + (k & 7) * 2);
}

// ---------------- weight blob (pre-split hi/lo, pre-swizzled) ----------------
#define BO_ENC1 0
#define BO_ENC2 32768
#define BO_RES1 163840
#define BO_RES2 294912
#define BO_RES3 360448
#define BO_POL2 491520
#define BO_EXP1 557056
#define BO_EXP2 2392064
#define BLOB_BYTES 4227072
__device__ __align__(16) uint8_t g_blob[BLOB_BYTES];

struct RefSeg { const float* src; int off; int N; int K; };
__global__ void reformat_all(RefSeg s0, RefSeg s1, RefSeg s2, RefSeg s3,
                             RefSeg s4, RefSeg s5, RefSeg s6, RefSeg s7)
{
    int idx = blockIdx.x * blockDim.x + threadIdx.x;
    RefSeg s; int local;
    if      (idx <   8192) { s = s0; local = idx; }
    else if (idx <  40960) { s = s1; local = idx - 8192; }
    else if (idx <  73728) { s = s2; local = idx - 40960; }
    else if (idx <  90112) { s = s3; local = idx - 73728; }
    else if (idx < 122880) { s = s4; local = idx - 90112; }
    else if (idx < 139264) { s = s5; local = idx - 122880; }
    else if (idx < 598016) { s = s6; local = idx - 139264; }
    else if (idx < 1056768){ s = s7; local = idx - 598016; }
    else return;
    const int N = s.N, K = s.K;
    int k  = local % K;
    int n  = (local / K) % N;
    int nb = local / (K * N);
    float w = s.src[local];
    __nv_bfloat16 h = __float2bfloat16(w);
    __nv_bfloat16 l = __float2bfloat16(w - __bfloat162float(h));
    int per_nb = (K / 64) * 2 * (N * 128);
    int kc = k >> 6, kk = k & 63;
    int base = s.off + nb * per_nb + kc * 2 * (N * 128);
    uint32_t byte = (uint32_t)n * 128u + (uint32_t)((((kk >> 3) ^ (n & 7)) << 4) + (kk & 7) * 2);
    *(__nv_bfloat16*)(g_blob + base + byte)           = h;
    *(__nv_bfloat16*)(g_blob + base + N * 128 + byte) = l;
}

// ---------------- SMEM layout (bytes) ----------------
#define SMB_W0    0
#define SMB_W1    32768
#define SMB_ABH   65536     // A_big hi [64][256] bf16
#define SMB_ABL   98304
#define SMB_AEH   131072    // A_exp hi [64][<=256] bf16
#define SMB_AEL   163840
#define SMB_XS    196608    // [4][64] f32
#define SMB_PROBS 197632
#define SMB_YACC  199424
#define SMB_SCR   199680    // [4][64] f32
#define SMB_TOTAL 200704

// ---------------- fused MMA layer (cp.async double-buffered fills) ----------------
// 8 warps: warp_m = warp&1 (32 rows via mt=2), warp_n = warp>>1 (N/4 cols, NT=8..4)
// MODE 0: sin->dest  1: relu->dest  2: relu(D+b+dest)->dest  3: sin·extra -> scr
template <int K, int N, int MODE, int SKA, int SKD>
static __device__ void layer(char* smem, const uint8_t* blob,
                             uint32_t aHi, uint32_t aLo,
                             char* dHi, char* dLo,
                             const float* bias, const float* extra)
{
    constexpr int FILLS = (K / 64) * 2;
    constexpr int LD = N / 32;      // 16B cp.asyncs per thread per fill
    constexpr int NT = N / 32;      // 8-wide n tiles per warp
    const int tid = threadIdx.x, lane = tid & 31, warp = tid >> 5;
    const int warp_m = warp & 1, warp_n = warp >> 1;
    const int nh = warp_n * (N / 4);

    float d[2][NT][4];
#pragma unroll
    for (int mt = 0; mt < 2; mt++)
#pragma unroll
        for (int nt = 0; nt < NT; nt++)
#pragma unroll
            for (int i = 0; i < 4; i++) d[mt][nt][i] = 0.0f;

    const int g = lane >> 3;
    const int mlocal = (lane & 7) + (g & 1) * 8;
    const int chA = g >> 1;
    const int bi = lane & 7, bsel = (lane >> 3) & 1;
    const uint32_t wsm0 = smem_u32(smem + SMB_W0);
    const uint32_t wsm1 = smem_u32(smem + SMB_W1);

    // prologue: fill 0 in flight
    {
        const char* src = (const char*)blob;
#pragma unroll
        for (int l = 0; l < LD; l++)
            cpasync16(wsm0 + (tid + NTHREADS * l) * 16, src + (tid + NTHREADS * l) * 16);
        CP_COMMIT();
    }

    for (int f = 0; f < FILLS; f++) {
        CP_WAIT0();
        __syncthreads();            // fill f visible; all MMAs on fill f-1 done
        if (f + 1 < FILLS) {        // overwrite buf holding fill f-1 (safe)
            const uint32_t dst = (f & 1) ? wsm0 : wsm1;
            const char* src = (const char*)blob + (size_t)(f + 1) * (N * 128);
#pragma unroll
            for (int l = 0; l < LD; l++)
                cpasync16(dst + (tid + NTHREADS * l) * 16, src + (tid + NTHREADS * l) * 16);
            CP_COMMIT();
        }
        const uint32_t wb = (f & 1) ? wsm1 : wsm0;
        const int kc = f >> 1, whalf = f & 1;
#pragma unroll
        for (int kk4 = 0; kk4 < 4; kk4++) {
            const int k0 = kc * 64 + kk4 * 16;
            uint32_t ah[2][4], al[2][4];
#pragma unroll
            for (int mt = 0; mt < 2; mt++) {
                const int m = warp_m * 32 + mt * 16 + mlocal;
                const uint32_t off = (uint32_t)m * (uint32_t)(SKA * 2)
                    + (uint32_t)(((((k0 >> 3) + chA) ^ (m & 7)) << 4));
                ldsm_x4(ah[mt], aHi + off);
                if (!whalf) ldsm_x4(al[mt], aLo + off);
            }
#pragma unroll
            for (int nt = 0; nt < NT; nt++) {
                const int n = nh + nt * 8 + bi;
                const uint32_t boff = (uint32_t)n * 128u
                    + (uint32_t)((((kk4 * 2 + bsel) ^ (n & 7)) << 4));
                uint32_t b[2];
                ldsm_x2(b, wb + boff);
                mma16816(d[0][nt], ah[0], b);
                mma16816(d[1][nt], ah[1], b);
                if (!whalf) {
                    mma16816(d[0][nt], al[0], b);
                    mma16816(d[1][nt], al[1], b);
                }
            }
        }
    }
    __syncthreads();   // all A reads complete before epilogue writes

    float pred[2][2] = {{0.0f, 0.0f}, {0.0f, 0.0f}};
#pragma unroll
    for (int mt = 0; mt < 2; mt++) {
        const int m1 = warp_m * 32 + mt * 16 + (lane >> 2);
        const int m2 = m1 + 8;
#pragma unroll
        for (int nt = 0; nt < NT; nt++) {
            const int nc = nh + nt * 8 + 2 * (lane & 3);
            const float b0 = __ldg(bias + nc), b1 = __ldg(bias + nc + 1);
            float v00 = d[mt][nt][0] + b0, v01 = d[mt][nt][1] + b1;
            float v10 = d[mt][nt][2] + b0, v11 = d[mt][nt][3] + b1;
            if (MODE == 3) {
                const float w0 = __ldg(extra + nc), w1 = __ldg(extra + nc + 1);
                pred[mt][0] += w0 * __sinf(OMEGA_F * v00) + w1 * __sinf(OMEGA_F * v01);
                pred[mt][1] += w0 * __sinf(OMEGA_F * v10) + w1 * __sinf(OMEGA_F * v11);
            } else {
                const uint32_t o1 = abyteA(m1, nc, SKD);
                const uint32_t o2 = abyteA(m2, nc, SKD);
                if (MODE == 2) {
                    uint32_t hh = *(uint32_t*)(dHi + o1), ll = *(uint32_t*)(dLo + o1);
                    v00 += join_w(hh, ll, 0); v01 += join_w(hh, ll, 1);
                    hh = *(uint32_t*)(dHi + o2); ll = *(uint32_t*)(dLo + o2);
                    v10 += join_w(hh, ll, 0); v11 += join_w(hh, ll, 1);
                }
                float s00, s01, s10, s11;
                if (MODE == 0) {
                    s00 = __sinf(OMEGA_F * v00); s01 = __sinf(OMEGA_F * v01);
                    s10 = __sinf(OMEGA_F * v10); s11 = __sinf(OMEGA_F * v11);
                } else {
                    s00 = fmaxf(v00, 0.0f); s01 = fmaxf(v01, 0.0f);
                    s10 = fmaxf(v10, 0.0f); s11 = fmaxf(v11, 0.0f);
                }
                uint32_t hi, lo;
                split_pair(s00, s01, hi, lo);
                *(uint32_t*)(dHi + o1) = hi; *(uint32_t*)(dLo + o1) = lo;
                split_pair(s10, s11, hi, lo);
                *(uint32_t*)(dHi + o2) = hi; *(uint32_t*)(dLo + o2) = lo;
            }
        }
    }
    if (MODE == 3) {
        float* scr = (float*)(smem + SMB_SCR);
#pragma unroll
        for (int mt = 0; mt < 2; mt++)
#pragma unroll
            for (int h = 0; h < 2; h++) {
                float p = pred[mt][h];
                p += __shfl_xor_sync(0xFFFFFFFFu, p, 1);
                p += __shfl_xor_sync(0xFFFFFFFFu, p, 2);
                if ((lane & 3) == 0)
                    scr[warp_n * 64 + warp_m * 32 + mt * 16 + (lane >> 2) + h * 8] = p;
            }
    }
}

// ---------------- main kernel ----------------
__global__ void __launch_bounds__(NTHREADS)
moe_inr_kernel(
    const float* __restrict__ x,
    const float* __restrict__ enc_s1_b, const float* __restrict__ enc_s2_b,
    const float* __restrict__ res_fc1_b, const float* __restrict__ res_fc2_b,
    const float* __restrict__ res_fc3_b,
    const float* __restrict__ pol_s1_w, const float* __restrict__ pol_s1_b,
    const float* __restrict__ pol_s2_b,
    const float* __restrict__ gate_w, const float* __restrict__ gate_b,
    const float* __restrict__ exp_s1_b, const float* __restrict__ exp_s2_b,
    const float* __restrict__ exp_fin_w, const float* __restrict__ exp_fin_b,
    float* __restrict__ out)
{
    extern __shared__ char smem[];
    const int tid = threadIdx.x;
    const long long rowbase = (long long)blockIdx.x * TB;
    float* xs    = (float*)(smem + SMB_XS);
    float* probs = (float*)(smem + SMB_PROBS);
    float* yacc  = (float*)(smem + SMB_YACC);
    float* scr   = (float*)(smem + SMB_SCR);
    char* abh = smem + SMB_ABH; char* abl = smem + SMB_ABL;
    char* aeh = smem + SMB_AEH; char* ael = smem + SMB_AEL;
    const uint32_t uABH = smem_u32(abh), uABL = smem_u32(abl);
    const uint32_t uAEH = smem_u32(aeh), uAEL = smem_u32(ael);

    {
        int m = tid >> 2, dd = tid & 3;
        xs[dd * 64 + m] = x[(rowbase + m) * 4 + dd];
    }
    __syncthreads();

    // positional encoding -> A_big (SK=64)
    for (int i = tid; i < 2048; i += NTHREADS) {
        int m = i & 63, jp = i >> 6;
        int c0 = 2 * jp;
        float v[2];
#pragma unroll
        for (int t = 0; t < 2; t++) {
            int c = c0 + t, dd = c >> 4, f = c & 15;
            float ang = xs[dd * 64 + m] * exp2f((float)(f & 7)) * 3.14159265358979323846f;
            v[t] = (f < 8) ? sinf(ang) : cosf(ang);
        }
        uint32_t hi, lo;
        split_pair(v[0], v[1], hi, lo);
        uint32_t off = abyteA(m, c0, 64);
        *(uint32_t*)(abh + off) = hi;
        *(uint32_t*)(abl + off) = lo;
    }
    __syncthreads();

    // encoder
    layer< 64, 128, 0,  64, 128>(smem, g_blob + BO_ENC1, uABH, uABL, aeh, ael, enc_s1_b, nullptr);
    layer<128, 256, 0, 128, 256>(smem, g_blob + BO_ENC2, uAEH, uAEL, abh, abl, enc_s2_b, nullptr);
    layer<256, 128, 1, 256, 128>(smem, g_blob + BO_RES1, uABH, uABL, aeh, ael, res_fc1_b, nullptr);
    layer<128, 128, 1, 128, 128>(smem, g_blob + BO_RES2, uAEH, uAEL, aeh, ael, res_fc2_b, nullptr);
    layer<128, 256, 2, 128, 256>(smem, g_blob + BO_RES3, uAEH, uAEL, abh, abl, res_fc3_b, nullptr);
    __syncthreads();

    // pol_s1 (K=4) scalar -> A_exp (SK=128)
    for (int i = tid; i < 4096; i += NTHREADS) {
        int m = i & 63, np = i >> 6;
        int n0 = 2 * np;
        float x0 = xs[m], x1 = xs[64 + m], x2 = xs[128 + m], x3 = xs[192 + m];
        float4 w0 = __ldg((const float4*)pol_s1_w + n0);
        float4 w1 = __ldg((const float4*)pol_s1_w + n0 + 1);
        float z0 = __ldg(pol_s1_b + n0)     + x0 * w0.x + x1 * w0.y + x2 * w0.z + x3 * w0.w;
        float z1 = __ldg(pol_s1_b + n0 + 1) + x0 * w1.x + x1 * w1.y + x2 * w1.z + x3 * w1.w;
        uint32_t hi, lo;
        split_pair(__sinf(OMEGA_F * z0), __sinf(OMEGA_F * z1), hi, lo);
        uint32_t off = abyteA(m, n0, 128);
        *(uint32_t*)(aeh + off) = hi;
        *(uint32_t*)(ael + off) = lo;
    }
    __syncthreads();

    layer<128, 128, 0, 128, 128>(smem, g_blob + BO_POL2, uAEH, uAEL, aeh, ael, pol_s2_b, nullptr);
    __syncthreads();

    // gate + softmax (1 thread per row)
    if (tid < 64) {
        const int m = tid;
        float lg[7];
#pragma unroll
        for (int c = 0; c < 7; c++) lg[c] = __ldg(gate_b + c);
        for (int k2 = 0; k2 < 128; k2++) {
            uint32_t off = abyteA(m, 2 * k2, 256);
            uint32_t hh = *(uint32_t*)(abh + off), ll = *(uint32_t*)(abl + off);
            float e0 = join_w(hh, ll, 0), e1 = join_w(hh, ll, 1);
#pragma unroll
            for (int c = 0; c < 7; c++)
                lg[c] += e0 * __ldg(gate_w + c * 384 + 2 * k2)
                       + e1 * __ldg(gate_w + c * 384 + 2 * k2 + 1);
        }
        for (int k2 = 0; k2 < 64; k2++) {
            uint32_t off = abyteA(m, 2 * k2, 128);
            uint32_t hh = *(uint32_t*)(aeh + off), ll = *(uint32_t*)(ael + off);
            float p0 = join_w(hh, ll, 0), p1 = join_w(hh, ll, 1);
#pragma unroll
            for (int c = 0; c < 7; c++)
                lg[c] += p0 * __ldg(gate_w + c * 384 + 256 + 2 * k2)
                       + p1 * __ldg(gate_w + c * 384 + 256 + 2 * k2 + 1);
        }
        float mx = -1e30f;
#pragma unroll
        for (int c = 0; c < 7; c++) mx = fmaxf(mx, lg[c]);
        float s = 0.0f;
#pragma unroll
        for (int c = 0; c < 7; c++) { lg[c] = __expf(lg[c] - mx); s += lg[c]; }
        float inv = 1.0f / s;
#pragma unroll
        for (int c = 0; c < 7; c++) probs[c * 64 + m] = lg[c] * inv;
        yacc[m] = 0.0f;
    }
    __syncthreads();

    // experts
    for (int e = 0; e < 7; e++) {
        layer<256, 256, 0, 256, 256>(smem, g_blob + BO_EXP1 + e * 262144,
                                     uABH, uABL, aeh, ael, exp_s1_b + e * 256, nullptr);
        layer<256, 256, 3, 256, 256>(smem, g_blob + BO_EXP2 + e * 262144,
                                     uAEH, uAEL, nullptr, nullptr,
                                     exp_s2_b + e * 256, exp_fin_w + e * 256);
        __syncthreads();
        if (tid < 64) {
            float pred = scr[tid] + scr[64 + tid] + scr[128 + tid] + scr[192 + tid]
                       + __ldg(exp_fin_b + e);
            yacc[tid] += probs[e * 64 + tid] * pred;
        }
        __syncthreads();
    }

    if (tid < 64) out[rowbase + tid] = yacc[tid];
}

// ---------------- host ----------------
extern "C" void kernel_launch(void* const* d_in, const int* in_sizes, int n_in,
                              void* d_out, int out_size)
{
    const float* x         = (const float*)d_in[0];
    const float* enc_s1_w  = (const float*)d_in[1];
    const float* enc_s1_b  = (const float*)d_in[2];
    const float* enc_s2_w  = (const float*)d_in[3];
    const float* enc_s2_b  = (const float*)d_in[4];
    const float* res_fc1_w = (const float*)d_in[5];
    const float* res_fc1_b = (const float*)d_in[6];
    const float* res_fc2_w = (const float*)d_in[7];
    const float* res_fc2_b = (const float*)d_in[8];
    const float* res_fc3_w = (const float*)d_in[9];
    const float* res_fc3_b = (const float*)d_in[10];
    const float* pol_s1_w  = (const float*)d_in[11];
    const float* pol_s1_b  = (const float*)d_in[12];
    const float* pol_s2_w  = (const float*)d_in[13];
    const float* pol_s2_b  = (const float*)d_in[14];
    const float* gate_w    = (const float*)d_in[15];
    const float* gate_b    = (const float*)d_in[16];
    const float* exp_s1_w  = (const float*)d_in[17];
    const float* exp_s1_b  = (const float*)d_in[18];
    const float* exp_s2_w  = (const float*)d_in[19];
    const float* exp_s2_b  = (const float*)d_in[20];
    const float* exp_fin_w = (const float*)d_in[21];
    const float* exp_fin_b = (const float*)d_in[22];

    RefSeg s0 = {enc_s1_w,  BO_ENC1, 128,  64};
    RefSeg s1 = {enc_s2_w,  BO_ENC2, 256, 128};
    RefSeg s2 = {res_fc1_w, BO_RES1, 128, 256};
    RefSeg s3 = {res_fc2_w, BO_RES2, 128, 128};
    RefSeg s4 = {res_fc3_w, BO_RES3, 256, 128};
    RefSeg s5 = {pol_s2_w,  BO_POL2, 128, 128};
    RefSeg s6 = {exp_s1_w,  BO_EXP1, 256, 256};
    RefSeg s7 = {exp_s2_w,  BO_EXP2, 256, 256};
    reformat_all<<<(1056768 + 255) / 256, 256>>>(s0, s1, s2, s3, s4, s5, s6, s7);

    int B = in_sizes[0] / 4;
    int grid = B / TB;
    cudaFuncSetAttribute(moe_inr_kernel, cudaFuncAttributeMaxDynamicSharedMemorySize, SMB_TOTAL);
    moe_inr_kernel<<<grid, NTHREADS, SMB_TOTAL>>>(
        x, enc_s1_b, enc_s2_b, res_fc1_b, res_fc2_b, res_fc3_b,
        pol_s1_w, pol_s1_b, pol_s2_b, gate_w, gate_b,
        exp_s1_b, exp_s2_b, exp_fin_w, exp_fin_b, (float*)d_out);
}

// round 15
// speedup vs baseline: 1.2389x; 1.1270x over previous
#include <cuda_runtime.h>
#include <cuda_bf16.h>
#include <cstdint>

#define NTHREADS 256
#define TB       64
#define OMEGA_F  30.0f

// ---------------- helpers ----------------
static __device__ __forceinline__ uint32_t smem_u32(const void* p) {
    uint32_t a;
    asm("{ .reg .u64 t; cvta.to.shared.u64 t, %1; cvt.u32.u64 %0, t; }" : "=r"(a) : "l"(p));
    return a;
}
static __device__ __forceinline__ void ldsm_x4(uint32_t* r, uint32_t a) {
    asm volatile("ldmatrix.sync.aligned.m8n8.x4.shared.b16 {%0,%1,%2,%3}, [%4];"
        : "=r"(r[0]), "=r"(r[1]), "=r"(r[2]), "=r"(r[3]) : "r"(a));
}
static __device__ __forceinline__ void ldsm_x2(uint32_t* r, uint32_t a) {
    asm volatile("ldmatrix.sync.aligned.m8n8.x2.shared.b16 {%0,%1}, [%2];"
        : "=r"(r[0]), "=r"(r[1]) : "r"(a));
}
static __device__ __forceinline__ void mma16816(float* d, const uint32_t* a, const uint32_t* b) {
    asm volatile("mma.sync.aligned.m16n8k16.row.col.f32.bf16.bf16.f32 "
        "{%0,%1,%2,%3}, {%4,%5,%6,%7}, {%8,%9}, {%0,%1,%2,%3};"
        : "+f"(d[0]), "+f"(d[1]), "+f"(d[2]), "+f"(d[3])
        : "r"(a[0]), "r"(a[1]), "r"(a[2]), "r"(a[3]), "r"(b[0]), "r"(b[1]));
}
static __device__ __forceinline__ void cpasync16(uint32_t dst, const void* src) {
    asm volatile("cp.async.cg.shared.global [%0], [%1], 16;" :: "r"(dst), "l"(src));
}
#define CP_COMMIT() asm volatile("cp.async.commit_group;" ::: "memory")
#define CP_WAIT0()  asm volatile("cp.async.wait_group 0;" ::: "memory")

static __device__ __forceinline__ void split_pair(float a0, float a1, uint32_t& hi, uint32_t& lo) {
    __nv_bfloat16 h0 = __float2bfloat16(a0), h1 = __float2bfloat16(a1);
    __nv_bfloat16 q0 = __float2bfloat16(a0 - __bfloat162float(h0));
    __nv_bfloat16 q1 = __float2bfloat16(a1 - __bfloat162float(h1));
    hi = ((uint32_t)__bfloat16_as_ushort(h1) << 16) | __bfloat16_as_ushort(h0);
    lo = ((uint32_t)__bfloat16_as_ushort(q1) << 16) | __bfloat16_as_ushort(q0);
}
static __device__ __forceinline__ float join_w(uint32_t h, uint32_t l, int hi16) {
    unsigned short hs = hi16 ? (unsigned short)(h >> 16) : (unsigned short)(h & 0xFFFF);
    unsigned short ls = hi16 ? (unsigned short)(l >> 16) : (unsigned short)(l & 0xFFFF);
    return __bfloat162float(__ushort_as_bfloat16(hs)) + __bfloat162float(__ushort_as_bfloat16(ls));
}
static __device__ __forceinline__ uint32_t abyteA(int m, int k, int SK) {
    return (uint32_t)m * (uint32_t)(SK * 2)
         + (uint32_t)((((k >> 3) ^ (m & 7)) << 4) + (k & 7) * 2);
}

// ---------------- weight blob (pre-split hi/lo, pre-swizzled) ----------------
#define BO_ENC1 0
#define BO_ENC2 32768
#define BO_RES1 163840
#define BO_RES2 294912
#define BO_RES3 360448
#define BO_POL2 491520
#define BO_EXP1 557056
#define BO_EXP2 2392064
#define BLOB_BYTES 4227072
__device__ __align__(16) uint8_t g_blob[BLOB_BYTES];

struct RefSeg { const float* src; int off; int N; int K; };
__global__ void reformat_all(RefSeg s0, RefSeg s1, RefSeg s2, RefSeg s3,
                             RefSeg s4, RefSeg s5, RefSeg s6, RefSeg s7)
{
    int idx = blockIdx.x * blockDim.x + threadIdx.x;
    RefSeg s; int local;
    if      (idx <   8192) { s = s0; local = idx; }
    else if (idx <  40960) { s = s1; local = idx - 8192; }
    else if (idx <  73728) { s = s2; local = idx - 40960; }
    else if (idx <  90112) { s = s3; local = idx - 73728; }
    else if (idx < 122880) { s = s4; local = idx - 90112; }
    else if (idx < 139264) { s = s5; local = idx - 122880; }
    else if (idx < 598016) { s = s6; local = idx - 139264; }
    else if (idx < 1056768){ s = s7; local = idx - 598016; }
    else return;
    const int N = s.N, K = s.K;
    int k  = local % K;
    int n  = (local / K) % N;
    int nb = local / (K * N);
    float w = s.src[local];
    __nv_bfloat16 h = __float2bfloat16(w);
    __nv_bfloat16 l = __float2bfloat16(w - __bfloat162float(h));
    int per_nb = (K / 64) * 2 * (N * 128);
    int kc = k >> 6, kk = k & 63;
    int base = s.off + nb * per_nb + kc * 2 * (N * 128);
    uint32_t byte = (uint32_t)n * 128u + (uint32_t)((((kk >> 3) ^ (n & 7)) << 4) + (kk & 7) * 2);
    *(__nv_bfloat16*)(g_blob + base + byte)           = h;
    *(__nv_bfloat16*)(g_blob + base + N * 128 + byte) = l;
}

// ---------------- SMEM layout (bytes) ----------------
#define SMB_W0    0
#define SMB_W1    32768
#define SMB_ABH   65536     // A_big hi [64][256] bf16
#define SMB_ABL   98304
#define SMB_AEH   131072    // A_exp hi [64][<=256] bf16
#define SMB_AEL   163840
#define SMB_XS    196608    // [4][64] f32
#define SMB_PROBS 197632
#define SMB_YACC  199424
#define SMB_SCR   199680    // [4][64] f32
#define SMB_TOTAL 200704

// ---------------- fused MMA layer (cp.async fills, latency-spread MMA order) ----
// 8 warps: warp_m = warp&1 (32 rows via mt=2), warp_n = warp>>1 (N/4 cols)
// MODE 0: sin->dest  1: relu->dest  2: relu(D+b+dest)->dest  3: sin·extra -> scr
template <int K, int N, int MODE, int SKA, int SKD>
static __device__ void layer(char* smem, const uint8_t* blob,
                             uint32_t aHi, uint32_t aLo,
                             char* dHi, char* dLo,
                             const float* bias, const float* extra)
{
    constexpr int FILLS = (K / 64) * 2;
    constexpr int LD = N / 32;      // 16B cp.asyncs per thread per fill
    constexpr int NT = N / 32;      // 8-wide n tiles per warp
    const int tid = threadIdx.x, lane = tid & 31, warp = tid >> 5;
    const int warp_m = warp & 1, warp_n = warp >> 1;
    const int nh = warp_n * (N / 4);

    float d[2][NT][4];
#pragma unroll
    for (int mt = 0; mt < 2; mt++)
#pragma unroll
        for (int nt = 0; nt < NT; nt++)
#pragma unroll
            for (int i = 0; i < 4; i++) d[mt][nt][i] = 0.0f;

    const int g = lane >> 3;
    const int mlocal = (lane & 7) + (g & 1) * 8;
    const int chA = g >> 1;
    const int bi = lane & 7, bsel = (lane >> 3) & 1;
    const uint32_t wsm0 = smem_u32(smem + SMB_W0);
    const uint32_t wsm1 = smem_u32(smem + SMB_W1);

    // prologue: fill 0 in flight
    {
        const char* src = (const char*)blob;
#pragma unroll
        for (int l = 0; l < LD; l++)
            cpasync16(wsm0 + (tid + NTHREADS * l) * 16, src + (tid + NTHREADS * l) * 16);
        CP_COMMIT();
    }

    for (int f = 0; f < FILLS; f++) {
        CP_WAIT0();
        __syncthreads();            // fill f visible; all MMAs on fill f-1 done
        if (f + 1 < FILLS) {        // overwrite buf holding fill f-1 (safe)
            const uint32_t dst = (f & 1) ? wsm0 : wsm1;
            const char* src = (const char*)blob + (size_t)(f + 1) * (N * 128);
#pragma unroll
            for (int l = 0; l < LD; l++)
                cpasync16(dst + (tid + NTHREADS * l) * 16, src + (tid + NTHREADS * l) * 16);
            CP_COMMIT();
        }
        const uint32_t wb = (f & 1) ? wsm1 : wsm0;
        const int kc = f >> 1, whalf = f & 1;
#pragma unroll
        for (int kk4 = 0; kk4 < 4; kk4++) {
            const int k0 = kc * 64 + kk4 * 16;
            uint32_t ah[2][4], al[2][4];
#pragma unroll
            for (int mt = 0; mt < 2; mt++) {
                const int m = warp_m * 32 + mt * 16 + mlocal;
                const uint32_t off = (uint32_t)m * (uint32_t)(SKA * 2)
                    + (uint32_t)(((((k0 >> 3) + chA) ^ (m & 7)) << 4));
                ldsm_x4(ah[mt], aHi + off);
                if (!whalf) ldsm_x4(al[mt], aLo + off);
            }
            // pass 1: hi-term MMAs; cache B fragments in registers
            uint32_t b[NT][2];
#pragma unroll
            for (int nt = 0; nt < NT; nt++) {
                const int n = nh + nt * 8 + bi;
                const uint32_t boff = (uint32_t)n * 128u
                    + (uint32_t)((((kk4 * 2 + bsel) ^ (n & 7)) << 4));
                ldsm_x2(b[nt], wb + boff);
                mma16816(d[0][nt], ah[0], b[nt]);
                mma16816(d[1][nt], ah[1], b[nt]);
            }
            // pass 2: lo-term MMAs (same accumulators, >=16 MMAs later)
            if (!whalf) {
#pragma unroll
                for (int nt = 0; nt < NT; nt++) {
                    mma16816(d[0][nt], al[0], b[nt]);
                    mma16816(d[1][nt], al[1], b[nt]);
                }
            }
        }
    }
    __syncthreads();   // all A reads complete before epilogue writes

    float pred[2][2] = {{0.0f, 0.0f}, {0.0f, 0.0f}};
#pragma unroll
    for (int mt = 0; mt < 2; mt++) {
        const int m1 = warp_m * 32 + mt * 16 + (lane >> 2);
        const int m2 = m1 + 8;
#pragma unroll
        for (int nt = 0; nt < NT; nt++) {
            const int nc = nh + nt * 8 + 2 * (lane & 3);
            const float b0 = __ldg(bias + nc), b1 = __ldg(bias + nc + 1);
            float v00 = d[mt][nt][0] + b0, v01 = d[mt][nt][1] + b1;
            float v10 = d[mt][nt][2] + b0, v11 = d[mt][nt][3] + b1;
            if (MODE == 3) {
                const float w0 = __ldg(extra + nc), w1 = __ldg(extra + nc + 1);
                pred[mt][0] += w0 * __sinf(OMEGA_F * v00) + w1 * __sinf(OMEGA_F * v01);
                pred[mt][1] += w0 * __sinf(OMEGA_F * v10) + w1 * __sinf(OMEGA_F * v11);
            } else {
                const uint32_t o1 = abyteA(m1, nc, SKD);
                const uint32_t o2 = abyteA(m2, nc, SKD);
                if (MODE == 2) {
                    uint32_t hh = *(uint32_t*)(dHi + o1), ll = *(uint32_t*)(dLo + o1);
                    v00 += join_w(hh, ll, 0); v01 += join_w(hh, ll, 1);
                    hh = *(uint32_t*)(dHi + o2); ll = *(uint32_t*)(dLo + o2);
                    v10 += join_w(hh, ll, 0); v11 += join_w(hh, ll, 1);
                }
                float s00, s01, s10, s11;
                if (MODE == 0) {
                    s00 = __sinf(OMEGA_F * v00); s01 = __sinf(OMEGA_F * v01);
                    s10 = __sinf(OMEGA_F * v10); s11 = __sinf(OMEGA_F * v11);
                } else {
                    s00 = fmaxf(v00, 0.0f); s01 = fmaxf(v01, 0.0f);
                    s10 = fmaxf(v10, 0.0f); s11 = fmaxf(v11, 0.0f);
                }
                uint32_t hi, lo;
                split_pair(s00, s01, hi, lo);
                *(uint32_t*)(dHi + o1) = hi; *(uint32_t*)(dLo + o1) = lo;
                split_pair(s10, s11, hi, lo);
                *(uint32_t*)(dHi + o2) = hi; *(uint32_t*)(dLo + o2) = lo;
            }
        }
    }
    if (MODE == 3) {
        float* scr = (float*)(smem + SMB_SCR);
#pragma unroll
        for (int mt = 0; mt < 2; mt++)
#pragma unroll
            for (int h = 0; h < 2; h++) {
                float p = pred[mt][h];
                p += __shfl_xor_sync(0xFFFFFFFFu, p, 1);
                p += __shfl_xor_sync(0xFFFFFFFFu, p, 2);
                if ((lane & 3) == 0)
                    scr[warp_n * 64 + warp_m * 32 + mt * 16 + (lane >> 2) + h * 8] = p;
            }
    }
}

// ---------------- main kernel ----------------
__global__ void __launch_bounds__(NTHREADS)
moe_inr_kernel(
    const float* __restrict__ x,
    const float* __restrict__ enc_s1_b, const float* __restrict__ enc_s2_b,
    const float* __restrict__ res_fc1_b, const float* __restrict__ res_fc2_b,
    const float* __restrict__ res_fc3_b,
    const float* __restrict__ pol_s1_w, const float* __restrict__ pol_s1_b,
    const float* __restrict__ pol_s2_b,
    const float* __restrict__ gate_w, const float* __restrict__ gate_b,
    const float* __restrict__ exp_s1_b, const float* __restrict__ exp_s2_b,
    const float* __restrict__ exp_fin_w, const float* __restrict__ exp_fin_b,
    float* __restrict__ out)
{
    extern __shared__ char smem[];
    const int tid = threadIdx.x;
    const long long rowbase = (long long)blockIdx.x * TB;
    float* xs    = (float*)(smem + SMB_XS);
    float* probs = (float*)(smem + SMB_PROBS);
    float* yacc  = (float*)(smem + SMB_YACC);
    float* scr   = (float*)(smem + SMB_SCR);
    char* abh = smem + SMB_ABH; char* abl = smem + SMB_ABL;
    char* aeh = smem + SMB_AEH; char* ael = smem + SMB_AEL;
    const uint32_t uABH = smem_u32(abh), uABL = smem_u32(abl);
    const uint32_t uAEH = smem_u32(aeh), uAEL = smem_u32(ael);

    {
        int m = tid >> 2, dd = tid & 3;
        xs[dd * 64 + m] = x[(rowbase + m) * 4 + dd];
    }
    __syncthreads();

    // positional encoding -> A_big (SK=64)
    for (int i = tid; i < 2048; i += NTHREADS) {
        int m = i & 63, jp = i >> 6;
        int c0 = 2 * jp;
        float v[2];
#pragma unroll
        for (int t = 0; t < 2; t++) {
            int c = c0 + t, dd = c >> 4, f = c & 15;
            float ang = xs[dd * 64 + m] * exp2f((float)(f & 7)) * 3.14159265358979323846f;
            v[t] = (f < 8) ? sinf(ang) : cosf(ang);
        }
        uint32_t hi, lo;
        split_pair(v[0], v[1], hi, lo);
        uint32_t off = abyteA(m, c0, 64);
        *(uint32_t*)(abh + off) = hi;
        *(uint32_t*)(abl + off) = lo;
    }
    __syncthreads();

    // encoder
    layer< 64, 128, 0,  64, 128>(smem, g_blob + BO_ENC1, uABH, uABL, aeh, ael, enc_s1_b, nullptr);
    layer<128, 256, 0, 128, 256>(smem, g_blob + BO_ENC2, uAEH, uAEL, abh, abl, enc_s2_b, nullptr);
    layer<256, 128, 1, 256, 128>(smem, g_blob + BO_RES1, uABH, uABL, aeh, ael, res_fc1_b, nullptr);
    layer<128, 128, 1, 128, 128>(smem, g_blob + BO_RES2, uAEH, uAEL, aeh, ael, res_fc2_b, nullptr);
    layer<128, 256, 2, 128, 256>(smem, g_blob + BO_RES3, uAEH, uAEL, abh, abl, res_fc3_b, nullptr);
    __syncthreads();

    // pol_s1 (K=4) scalar -> A_exp (SK=128)
    for (int i = tid; i < 4096; i += NTHREADS) {
        int m = i & 63, np = i >> 6;
        int n0 = 2 * np;
        float x0 = xs[m], x1 = xs[64 + m], x2 = xs[128 + m], x3 = xs[192 + m];
        float4 w0 = __ldg((const float4*)pol_s1_w + n0);
        float4 w1 = __ldg((const float4*)pol_s1_w + n0 + 1);
        float z0 = __ldg(pol_s1_b + n0)     + x0 * w0.x + x1 * w0.y + x2 * w0.z + x3 * w0.w;
        float z1 = __ldg(pol_s1_b + n0 + 1) + x0 * w1.x + x1 * w1.y + x2 * w1.z + x3 * w1.w;
        uint32_t hi, lo;
        split_pair(__sinf(OMEGA_F * z0), __sinf(OMEGA_F * z1), hi, lo);
        uint32_t off = abyteA(m, n0, 128);
        *(uint32_t*)(aeh + off) = hi;
        *(uint32_t*)(ael + off) = lo;
    }
    __syncthreads();

    layer<128, 128, 0, 128, 128>(smem, g_blob + BO_POL2, uAEH, uAEL, aeh, ael, pol_s2_b, nullptr);
    __syncthreads();

    // gate + softmax (1 thread per row)
    if (tid < 64) {
        const int m = tid;
        float lg[7];
#pragma unroll
        for (int c = 0; c < 7; c++) lg[c] = __ldg(gate_b + c);
        for (int k2 = 0; k2 < 128; k2++) {
            uint32_t off = abyteA(m, 2 * k2, 256);
            uint32_t hh = *(uint32_t*)(abh + off), ll = *(uint32_t*)(abl + off);
            float e0 = join_w(hh, ll, 0), e1 = join_w(hh, ll, 1);
#pragma unroll
            for (int c = 0; c < 7; c++)
                lg[c] += e0 * __ldg(gate_w + c * 384 + 2 * k2)
                       + e1 * __ldg(gate_w + c * 384 + 2 * k2 + 1);
        }
        for (int k2 = 0; k2 < 64; k2++) {
            uint32_t off = abyteA(m, 2 * k2, 128);
            uint32_t hh = *(uint32_t*)(aeh + off), ll = *(uint32_t*)(ael + off);
            float p0 = join_w(hh, ll, 0), p1 = join_w(hh, ll, 1);
#pragma unroll
            for (int c = 0; c < 7; c++)
                lg[c] += p0 * __ldg(gate_w + c * 384 + 256 + 2 * k2)
                       + p1 * __ldg(gate_w + c * 384 + 256 + 2 * k2 + 1);
        }
        float mx = -1e30f;
#pragma unroll
        for (int c = 0; c < 7; c++) mx = fmaxf(mx, lg[c]);
        float s = 0.0f;
#pragma unroll
        for (int c = 0; c < 7; c++) { lg[c] = __expf(lg[c] - mx); s += lg[c]; }
        float inv = 1.0f / s;
#pragma unroll
        for (int c = 0; c < 7; c++) probs[c * 64 + m] = lg[c] * inv;
        yacc[m] = 0.0f;
    }
    __syncthreads();

    // experts
    for (int e = 0; e < 7; e++) {
        layer<256, 256, 0, 256, 256>(smem, g_blob + BO_EXP1 + e * 262144,
                                     uABH, uABL, aeh, ael, exp_s1_b + e * 256, nullptr);
        layer<256, 256, 3, 256, 256>(smem, g_blob + BO_EXP2 + e * 262144,
                                     uAEH, uAEL, nullptr, nullptr,
                                     exp_s2_b + e * 256, exp_fin_w + e * 256);
        __syncthreads();
        if (tid < 64) {
            float pred = scr[tid] + scr[64 + tid] + scr[128 + tid] + scr[192 + tid]
                       + __ldg(exp_fin_b + e);
            yacc[tid] += probs[e * 64 + tid] * pred;
        }
        __syncthreads();
    }

    if (tid < 64) out[rowbase + tid] = yacc[tid];
}

// ---------------- host ----------------
extern "C" void kernel_launch(void* const* d_in, const int* in_sizes, int n_in,
                              void* d_out, int out_size)
{
    const float* x         = (const float*)d_in[0];
    const float* enc_s1_w  = (const float*)d_in[1];
    const float* enc_s1_b  = (const float*)d_in[2];
    const float* enc_s2_w  = (const float*)d_in[3];
    const float* enc_s2_b  = (const float*)d_in[4];
    const float* res_fc1_w = (const float*)d_in[5];
    const float* res_fc1_b = (const float*)d_in[6];
    const float* res_fc2_w = (const float*)d_in[7];
    const float* res_fc2_b = (const float*)d_in[8];
    const float* res_fc3_w = (const float*)d_in[9];
    const float* res_fc3_b = (const float*)d_in[10];
    const float* pol_s1_w  = (const float*)d_in[11];
    const float* pol_s1_b  = (const float*)d_in[12];
    const float* pol_s2_w  = (const float*)d_in[13];
    const float* pol_s2_b  = (const float*)d_in[14];
    const float* gate_w    = (const float*)d_in[15];
    const float* gate_b    = (const float*)d_in[16];
    const float* exp_s1_w  = (const float*)d_in[17];
    const float* exp_s1_b  = (const float*)d_in[18];
    const float* exp_s2_w  = (const float*)d_in[19];
    const float* exp_s2_b  = (const float*)d_in[20];
    const float* exp_fin_w = (const float*)d_in[21];
    const float* exp_fin_b = (const float*)d_in[22];

    RefSeg s0 = {enc_s1_w,  BO_ENC1, 128,  64};
    RefSeg s1 = {enc_s2_w,  BO_ENC2, 256, 128};
    RefSeg s2 = {res_fc1_w, BO_RES1, 128, 256};
    RefSeg s3 = {res_fc2_w, BO_RES2, 128, 128};
    RefSeg s4 = {res_fc3_w, BO_RES3, 256, 128};
    RefSeg s5 = {pol_s2_w,  BO_POL2, 128, 128};
    RefSeg s6 = {exp_s1_w,  BO_EXP1, 256, 256};
    RefSeg s7 = {exp_s2_w,  BO_EXP2, 256, 256};
    reformat_all<<<(1056768 + 255) / 256, 256>>>(s0, s1, s2, s3, s4, s5, s6, s7);

    int B = in_sizes[0] / 4;
    int grid = B / TB;
    cudaFuncSetAttribute(moe_inr_kernel, cudaFuncAttributeMaxDynamicSharedMemorySize, SMB_TOTAL);
    moe_inr_kernel<<<grid, NTHREADS, SMB_TOTAL>>>(
        x, enc_s1_b, enc_s2_b, res_fc1_b, res_fc2_b, res_fc3_b,
        pol_s1_w, pol_s1_b, pol_s2_b, gate_w, gate_b,
        exp_s1_b, exp_s2_b, exp_fin_w, exp_fin_b, (float*)d_out);
}

// round 16
// speedup vs baseline: 1.2534x; 1.0118x over previous
#include <cuda_runtime.h>
#include <cuda_bf16.h>
#include <cstdint>

#define NTHREADS 512
#define TB       64
#define OMEGA_F  30.0f

// ---------------- helpers ----------------
static __device__ __forceinline__ uint32_t smem_u32(const void* p) {
    uint32_t a;
    asm("{ .reg .u64 t; cvta.to.shared.u64 t, %1; cvt.u32.u64 %0, t; }" : "=r"(a) : "l"(p));
    return a;
}
static __device__ __forceinline__ void ldsm_x4(uint32_t* r, uint32_t a) {
    asm volatile("ldmatrix.sync.aligned.m8n8.x4.shared.b16 {%0,%1,%2,%3}, [%4];"
        : "=r"(r[0]), "=r"(r[1]), "=r"(r[2]), "=r"(r[3]) : "r"(a));
}
static __device__ __forceinline__ void ldsm_x2(uint32_t* r, uint32_t a) {
    asm volatile("ldmatrix.sync.aligned.m8n8.x2.shared.b16 {%0,%1}, [%2];"
        : "=r"(r[0]), "=r"(r[1]) : "r"(a));
}
static __device__ __forceinline__ void mma16816(float* d, const uint32_t* a, const uint32_t* b) {
    asm volatile("mma.sync.aligned.m16n8k16.row.col.f32.bf16.bf16.f32 "
        "{%0,%1,%2,%3}, {%4,%5,%6,%7}, {%8,%9}, {%0,%1,%2,%3};"
        : "+f"(d[0]), "+f"(d[1]), "+f"(d[2]), "+f"(d[3])
        : "r"(a[0]), "r"(a[1]), "r"(a[2]), "r"(a[3]), "r"(b[0]), "r"(b[1]));
}
static __device__ __forceinline__ void cpasync16(uint32_t dst, const void* src) {
    asm volatile("cp.async.cg.shared.global [%0], [%1], 16;" :: "r"(dst), "l"(src));
}
#define CP_COMMIT() asm volatile("cp.async.commit_group;" ::: "memory")
#define CP_WAIT0()  asm volatile("cp.async.wait_group 0;" ::: "memory")

static __device__ __forceinline__ void split_pair(float a0, float a1, uint32_t& hi, uint32_t& lo) {
    __nv_bfloat16 h0 = __float2bfloat16(a0), h1 = __float2bfloat16(a1);
    __nv_bfloat16 q0 = __float2bfloat16(a0 - __bfloat162float(h0));
    __nv_bfloat16 q1 = __float2bfloat16(a1 - __bfloat162float(h1));
    hi = ((uint32_t)__bfloat16_as_ushort(h1) << 16) | __bfloat16_as_ushort(h0);
    lo = ((uint32_t)__bfloat16_as_ushort(q1) << 16) | __bfloat16_as_ushort(q0);
}
static __device__ __forceinline__ float join_w(uint32_t h, uint32_t l, int hi16) {
    unsigned short hs = hi16 ? (unsigned short)(h >> 16) : (unsigned short)(h & 0xFFFF);
    unsigned short ls = hi16 ? (unsigned short)(l >> 16) : (unsigned short)(l & 0xFFFF);
    return __bfloat162float(__ushort_as_bfloat16(hs)) + __bfloat162float(__ushort_as_bfloat16(ls));
}
static __device__ __forceinline__ uint32_t abyteA(int m, int k, int SK) {
    return (uint32_t)m * (uint32_t)(SK * 2)
         + (uint32_t)((((k >> 3) ^ (m & 7)) << 4) + (k & 7) * 2);
}

// ---------------- weight blob (pre-split hi/lo, pre-swizzled) ----------------
#define BO_ENC1 0
#define BO_ENC2 32768
#define BO_RES1 163840
#define BO_RES2 294912
#define BO_RES3 360448
#define BO_POL2 491520
#define BO_EXP1 557056
#define BO_EXP2 2392064
#define BLOB_BYTES 4227072
__device__ __align__(16) uint8_t g_blob[BLOB_BYTES];

struct RefSeg { const float* src; int off; int N; int K; };
__global__ void reformat_all(RefSeg s0, RefSeg s1, RefSeg s2, RefSeg s3,
                             RefSeg s4, RefSeg s5, RefSeg s6, RefSeg s7)
{
    int idx = blockIdx.x * blockDim.x + threadIdx.x;
    RefSeg s; int local;
    if      (idx <   8192) { s = s0; local = idx; }
    else if (idx <  40960) { s = s1; local = idx - 8192; }
    else if (idx <  73728) { s = s2; local = idx - 40960; }
    else if (idx <  90112) { s = s3; local = idx - 73728; }
    else if (idx < 122880) { s = s4; local = idx - 90112; }
    else if (idx < 139264) { s = s5; local = idx - 122880; }
    else if (idx < 598016) { s = s6; local = idx - 139264; }
    else if (idx < 1056768){ s = s7; local = idx - 598016; }
    else return;
    const int N = s.N, K = s.K;
    int k  = local % K;
    int n  = (local / K) % N;
    int nb = local / (K * N);
    float w = s.src[local];
    __nv_bfloat16 h = __float2bfloat16(w);
    __nv_bfloat16 l = __float2bfloat16(w - __bfloat162float(h));
    int per_nb = (K / 64) * 2 * (N * 128);
    int kc = k >> 6, kk = k & 63;
    int base = s.off + nb * per_nb + kc * 2 * (N * 128);
    uint32_t byte = (uint32_t)n * 128u + (uint32_t)((((kk >> 3) ^ (n & 7)) << 4) + (kk & 7) * 2);
    *(__nv_bfloat16*)(g_blob + base + byte)           = h;
    *(__nv_bfloat16*)(g_blob + base + N * 128 + byte) = l;
}

// ---------------- SMEM layout (bytes) ----------------
#define SMB_W0    0
#define SMB_W1    32768
#define SMB_ABH   65536     // A_big hi [64][256] bf16
#define SMB_ABL   98304
#define SMB_AEH   131072    // A_exp hi [64][<=256] bf16
#define SMB_AEL   163840
#define SMB_XS    196608    // [4][64] f32
#define SMB_PROBS 197632
#define SMB_YACC  199424
#define SMB_SCR   199680    // [8][64] f32
#define SMB_TOTAL 201728

// ---------------- fused MMA layer (cp.async fills, 16 warps 2m x 8n) ----------
// warp_m = warp&1 (32 rows via mt=2), warp_n = warp>>1 (N/8 cols, NT=N/64)
// MODE 0: sin->dest  1: relu->dest  2: relu(D+b+dest)->dest  3: sin·extra -> scr
template <int K, int N, int MODE, int SKA, int SKD>
static __device__ void layer(char* smem, const uint8_t* blob,
                             uint32_t aHi, uint32_t aLo,
                             char* dHi, char* dLo,
                             const float* bias, const float* extra)
{
    constexpr int FILLS = (K / 64) * 2;
    constexpr int LD = N / 64;      // 16B cp.asyncs per thread per fill
    constexpr int NT = N / 64;      // 8-wide n tiles per warp (N/8 cols per warp)
    const int tid = threadIdx.x, lane = tid & 31, warp = tid >> 5;
    const int warp_m = warp & 1, warp_n = warp >> 1;
    const int nh = warp_n * (N / 8);

    float d[2][NT][4];
#pragma unroll
    for (int mt = 0; mt < 2; mt++)
#pragma unroll
        for (int nt = 0; nt < NT; nt++)
#pragma unroll
            for (int i = 0; i < 4; i++) d[mt][nt][i] = 0.0f;

    const int g = lane >> 3;
    const int mlocal = (lane & 7) + (g & 1) * 8;
    const int chA = g >> 1;
    const int bi = lane & 7, bsel = (lane >> 3) & 1;
    const uint32_t wsm0 = smem_u32(smem + SMB_W0);
    const uint32_t wsm1 = smem_u32(smem + SMB_W1);

    // prologue: fill 0 in flight
    {
        const char* src = (const char*)blob;
#pragma unroll
        for (int l = 0; l < LD; l++)
            cpasync16(wsm0 + (tid + NTHREADS * l) * 16, src + (tid + NTHREADS * l) * 16);
        CP_COMMIT();
    }

    for (int f = 0; f < FILLS; f++) {
        CP_WAIT0();
        __syncthreads();            // fill f visible; all MMAs on fill f-1 done
        if (f + 1 < FILLS) {        // overwrite buf holding fill f-1 (safe)
            const uint32_t dst = (f & 1) ? wsm0 : wsm1;
            const char* src = (const char*)blob + (size_t)(f + 1) * (N * 128);
#pragma unroll
            for (int l = 0; l < LD; l++)
                cpasync16(dst + (tid + NTHREADS * l) * 16, src + (tid + NTHREADS * l) * 16);
            CP_COMMIT();
        }
        const uint32_t wb = (f & 1) ? wsm1 : wsm0;
        const int kc = f >> 1, whalf = f & 1;
#pragma unroll
        for (int kk4 = 0; kk4 < 4; kk4++) {
            const int k0 = kc * 64 + kk4 * 16;
            uint32_t ah[2][4], al[2][4];
#pragma unroll
            for (int mt = 0; mt < 2; mt++) {
                const int m = warp_m * 32 + mt * 16 + mlocal;
                const uint32_t off = (uint32_t)m * (uint32_t)(SKA * 2)
                    + (uint32_t)(((((k0 >> 3) + chA) ^ (m & 7)) << 4));
                ldsm_x4(ah[mt], aHi + off);
                if (!whalf) ldsm_x4(al[mt], aLo + off);
            }
            // pass 1: hi-term MMAs; cache B fragments in registers
            uint32_t b[NT][2];
#pragma unroll
            for (int nt = 0; nt < NT; nt++) {
                const int n = nh + nt * 8 + bi;
                const uint32_t boff = (uint32_t)n * 128u
                    + (uint32_t)((((kk4 * 2 + bsel) ^ (n & 7)) << 4));
                ldsm_x2(b[nt], wb + boff);
                mma16816(d[0][nt], ah[0], b[nt]);
                mma16816(d[1][nt], ah[1], b[nt]);
            }
            // pass 2: lo-term MMAs (same accumulators, later in stream)
            if (!whalf) {
#pragma unroll
                for (int nt = 0; nt < NT; nt++) {
                    mma16816(d[0][nt], al[0], b[nt]);
                    mma16816(d[1][nt], al[1], b[nt]);
                }
            }
        }
    }
    __syncthreads();   // all A reads complete before epilogue writes

    float pred[2][2] = {{0.0f, 0.0f}, {0.0f, 0.0f}};
#pragma unroll
    for (int mt = 0; mt < 2; mt++) {
        const int m1 = warp_m * 32 + mt * 16 + (lane >> 2);
        const int m2 = m1 + 8;
#pragma unroll
        for (int nt = 0; nt < NT; nt++) {
            const int nc = nh + nt * 8 + 2 * (lane & 3);
            const float b0 = __ldg(bias + nc), b1 = __ldg(bias + nc + 1);
            float v00 = d[mt][nt][0] + b0, v01 = d[mt][nt][1] + b1;
            float v10 = d[mt][nt][2] + b0, v11 = d[mt][nt][3] + b1;
            if (MODE == 3) {
                const float w0 = __ldg(extra + nc), w1 = __ldg(extra + nc + 1);
                pred[mt][0] += w0 * __sinf(OMEGA_F * v00) + w1 * __sinf(OMEGA_F * v01);
                pred[mt][1] += w0 * __sinf(OMEGA_F * v10) + w1 * __sinf(OMEGA_F * v11);
            } else {
                const uint32_t o1 = abyteA(m1, nc, SKD);
                const uint32_t o2 = abyteA(m2, nc, SKD);
                if (MODE == 2) {
                    uint32_t hh = *(uint32_t*)(dHi + o1), ll = *(uint32_t*)(dLo + o1);
                    v00 += join_w(hh, ll, 0); v01 += join_w(hh, ll, 1);
                    hh = *(uint32_t*)(dHi + o2); ll = *(uint32_t*)(dLo + o2);
                    v10 += join_w(hh, ll, 0); v11 += join_w(hh, ll, 1);
                }
                float s00, s01, s10, s11;
                if (MODE == 0) {
                    s00 = __sinf(OMEGA_F * v00); s01 = __sinf(OMEGA_F * v01);
                    s10 = __sinf(OMEGA_F * v10); s11 = __sinf(OMEGA_F * v11);
                } else {
                    s00 = fmaxf(v00, 0.0f); s01 = fmaxf(v01, 0.0f);
                    s10 = fmaxf(v10, 0.0f); s11 = fmaxf(v11, 0.0f);
                }
                uint32_t hi, lo;
                split_pair(s00, s01, hi, lo);
                *(uint32_t*)(dHi + o1) = hi; *(uint32_t*)(dLo + o1) = lo;
                split_pair(s10, s11, hi, lo);
                *(uint32_t*)(dHi + o2) = hi; *(uint32_t*)(dLo + o2) = lo;
            }
        }
    }
    if (MODE == 3) {
        float* scr = (float*)(smem + SMB_SCR);
#pragma unroll
        for (int mt = 0; mt < 2; mt++)
#pragma unroll
            for (int h = 0; h < 2; h++) {
                float p = pred[mt][h];
                p += __shfl_xor_sync(0xFFFFFFFFu, p, 1);
                p += __shfl_xor_sync(0xFFFFFFFFu, p, 2);
                if ((lane & 3) == 0)
                    scr[warp_n * 64 + warp_m * 32 + mt * 16 + (lane >> 2) + h * 8] = p;
            }
    }
}

// ---------------- main kernel ----------------
__global__ void __launch_bounds__(NTHREADS)
moe_inr_kernel(
    const float* __restrict__ x,
    const float* __restrict__ enc_s1_b, const float* __restrict__ enc_s2_b,
    const float* __restrict__ res_fc1_b, const float* __restrict__ res_fc2_b,
    const float* __restrict__ res_fc3_b,
    const float* __restrict__ pol_s1_w, const float* __restrict__ pol_s1_b,
    const float* __restrict__ pol_s2_b,
    const float* __restrict__ gate_w, const float* __restrict__ gate_b,
    const float* __restrict__ exp_s1_b, const float* __restrict__ exp_s2_b,
    const float* __restrict__ exp_fin_w, const float* __restrict__ exp_fin_b,
    float* __restrict__ out)
{
    extern __shared__ char smem[];
    const int tid = threadIdx.x;
    const long long rowbase = (long long)blockIdx.x * TB;
    float* xs    = (float*)(smem + SMB_XS);
    float* probs = (float*)(smem + SMB_PROBS);
    float* yacc  = (float*)(smem + SMB_YACC);
    float* scr   = (float*)(smem + SMB_SCR);
    char* abh = smem + SMB_ABH; char* abl = smem + SMB_ABL;
    char* aeh = smem + SMB_AEH; char* ael = smem + SMB_AEL;
    const uint32_t uABH = smem_u32(abh), uABL = smem_u32(abl);
    const uint32_t uAEH = smem_u32(aeh), uAEL = smem_u32(ael);

    if (tid < 256) {
        int m = tid >> 2, dd = tid & 3;
        xs[dd * 64 + m] = x[(rowbase + m) * 4 + dd];
    }
    __syncthreads();

    // positional encoding -> A_big (SK=64)
    for (int i = tid; i < 2048; i += NTHREADS) {
        int m = i & 63, jp = i >> 6;
        int c0 = 2 * jp;
        float v[2];
#pragma unroll
        for (int t = 0; t < 2; t++) {
            int c = c0 + t, dd = c >> 4, f = c & 15;
            float ang = xs[dd * 64 + m] * exp2f((float)(f & 7)) * 3.14159265358979323846f;
            v[t] = (f < 8) ? sinf(ang) : cosf(ang);
        }
        uint32_t hi, lo;
        split_pair(v[0], v[1], hi, lo);
        uint32_t off = abyteA(m, c0, 64);
        *(uint32_t*)(abh + off) = hi;
        *(uint32_t*)(abl + off) = lo;
    }
    __syncthreads();

    // encoder
    layer< 64, 128, 0,  64, 128>(smem, g_blob + BO_ENC1, uABH, uABL, aeh, ael, enc_s1_b, nullptr);
    layer<128, 256, 0, 128, 256>(smem, g_blob + BO_ENC2, uAEH, uAEL, abh, abl, enc_s2_b, nullptr);
    layer<256, 128, 1, 256, 128>(smem, g_blob + BO_RES1, uABH, uABL, aeh, ael, res_fc1_b, nullptr);
    layer<128, 128, 1, 128, 128>(smem, g_blob + BO_RES2, uAEH, uAEL, aeh, ael, res_fc2_b, nullptr);
    layer<128, 256, 2, 128, 256>(smem, g_blob + BO_RES3, uAEH, uAEL, abh, abl, res_fc3_b, nullptr);
    __syncthreads();

    // pol_s1 (K=4) scalar -> A_exp (SK=128)
    for (int i = tid; i < 4096; i += NTHREADS) {
        int m = i & 63, np = i >> 6;
        int n0 = 2 * np;
        float x0 = xs[m], x1 = xs[64 + m], x2 = xs[128 + m], x3 = xs[192 + m];
        float4 w0 = __ldg((const float4*)pol_s1_w + n0);
        float4 w1 = __ldg((const float4*)pol_s1_w + n0 + 1);
        float z0 = __ldg(pol_s1_b + n0)     + x0 * w0.x + x1 * w0.y + x2 * w0.z + x3 * w0.w;
        float z1 = __ldg(pol_s1_b + n0 + 1) + x0 * w1.x + x1 * w1.y + x2 * w1.z + x3 * w1.w;
        uint32_t hi, lo;
        split_pair(__sinf(OMEGA_F * z0), __sinf(OMEGA_F * z1), hi, lo);
        uint32_t off = abyteA(m, n0, 128);
        *(uint32_t*)(aeh + off) = hi;
        *(uint32_t*)(ael + off) = lo;
    }
    __syncthreads();

    layer<128, 128, 0, 128, 128>(smem, g_blob + BO_POL2, uAEH, uAEL, aeh, ael, pol_s2_b, nullptr);
    __syncthreads();

    // gate + softmax (1 thread per row)
    if (tid < 64) {
        const int m = tid;
        float lg[7];
#pragma unroll
        for (int c = 0; c < 7; c++) lg[c] = __ldg(gate_b + c);
        for (int k2 = 0; k2 < 128; k2++) {
            uint32_t off = abyteA(m, 2 * k2, 256);
            uint32_t hh = *(uint32_t*)(abh + off), ll = *(uint32_t*)(abl + off);
            float e0 = join_w(hh, ll, 0), e1 = join_w(hh, ll, 1);
#pragma unroll
            for (int c = 0; c < 7; c++)
                lg[c] += e0 * __ldg(gate_w + c * 384 + 2 * k2)
                       + e1 * __ldg(gate_w + c * 384 + 2 * k2 + 1);
        }
        for (int k2 = 0; k2 < 64; k2++) {
            uint32_t off = abyteA(m, 2 * k2, 128);
            uint32_t hh = *(uint32_t*)(aeh + off), ll = *(uint32_t*)(ael + off);
            float p0 = join_w(hh, ll, 0), p1 = join_w(hh, ll, 1);
#pragma unroll
            for (int c = 0; c < 7; c++)
                lg[c] += p0 * __ldg(gate_w + c * 384 + 256 + 2 * k2)
                       + p1 * __ldg(gate_w + c * 384 + 256 + 2 * k2 + 1);
        }
        float mx = -1e30f;
#pragma unroll
        for (int c = 0; c < 7; c++) mx = fmaxf(mx, lg[c]);
        float s = 0.0f;
#pragma unroll
        for (int c = 0; c < 7; c++) { lg[c] = __expf(lg[c] - mx); s += lg[c]; }
        float inv = 1.0f / s;
#pragma unroll
        for (int c = 0; c < 7; c++) probs[c * 64 + m] = lg[c] * inv;
        yacc[m] = 0.0f;
    }
    __syncthreads();

    // experts
    for (int e = 0; e < 7; e++) {
        layer<256, 256, 0, 256, 256>(smem, g_blob + BO_EXP1 + e * 262144,
                                     uABH, uABL, aeh, ael, exp_s1_b + e * 256, nullptr);
        layer<256, 256, 3, 256, 256>(smem, g_blob + BO_EXP2 + e * 262144,
                                     uAEH, uAEL, nullptr, nullptr,
                                     exp_s2_b + e * 256, exp_fin_w + e * 256);
        __syncthreads();
        if (tid < 64) {
            float pred = __ldg(exp_fin_b + e);
#pragma unroll
            for (int p = 0; p < 8; p++) pred += scr[p * 64 + tid];
            yacc[tid] += probs[e * 64 + tid] * pred;
        }
        __syncthreads();
    }

    if (tid < 64) out[rowbase + tid] = yacc[tid];
}

// ---------------- host ----------------
extern "C" void kernel_launch(void* const* d_in, const int* in_sizes, int n_in,
                              void* d_out, int out_size)
{
    const float* x         = (const float*)d_in[0];
    const float* enc_s1_w  = (const float*)d_in[1];
    const float* enc_s1_b  = (const float*)d_in[2];
    const float* enc_s2_w  = (const float*)d_in[3];
    const float* enc_s2_b  = (const float*)d_in[4];
    const float* res_fc1_w = (const float*)d_in[5];
    const float* res_fc1_b = (const float*)d_in[6];
    const float* res_fc2_w = (const float*)d_in[7];
    const float* res_fc2_b = (const float*)d_in[8];
    const float* res_fc3_w = (const float*)d_in[9];
    const float* res_fc3_b = (const float*)d_in[10];
    const float* pol_s1_w  = (const float*)d_in[11];
    const float* pol_s1_b  = (const float*)d_in[12];
    const float* pol_s2_w  = (const float*)d_in[13];
    const float* pol_s2_b  = (const float*)d_in[14];
    const float* gate_w    = (const float*)d_in[15];
    const float* gate_b    = (const float*)d_in[16];
    const float* exp_s1_w  = (const float*)d_in[17];
    const float* exp_s1_b  = (const float*)d_in[18];
    const float* exp_s2_w  = (const float*)d_in[19];
    const float* exp_s2_b  = (const float*)d_in[20];
    const float* exp_fin_w = (const float*)d_in[21];
    const float* exp_fin_b = (const float*)d_in[22];

    RefSeg s0 = {enc_s1_w,  BO_ENC1, 128,  64};
    RefSeg s1 = {enc_s2_w,  BO_ENC2, 256, 128};
    RefSeg s2 = {res_fc1_w, BO_RES1, 128, 256};
    RefSeg s3 = {res_fc2_w, BO_RES2, 128, 128};
    RefSeg s4 = {res_fc3_w, BO_RES3, 256, 128};
    RefSeg s5 = {pol_s2_w,  BO_POL2, 128, 128};
    RefSeg s6 = {exp_s1_w,  BO_EXP1, 256, 256};
    RefSeg s7 = {exp_s2_w,  BO_EXP2, 256, 256};
    reformat_all<<<(1056768 + 255) / 256, 256>>>(s0, s1, s2, s3, s4, s5, s6, s7);

    int B = in_sizes[0] / 4;
    int grid = B / TB;
    cudaFuncSetAttribute(moe_inr_kernel, cudaFuncAttributeMaxDynamicSharedMemorySize, SMB_TOTAL);
    moe_inr_kernel<<<grid, NTHREADS, SMB_TOTAL>>>(
        x, enc_s1_b, enc_s2_b, res_fc1_b, res_fc2_b, res_fc3_b,
        pol_s1_w, pol_s1_b, pol_s2_b, gate_w, gate_b,
        exp_s1_b, exp_s2_b, exp_fin_w, exp_fin_b, (float*)d_out);
}